// round 3
// baseline (speedup 1.0000x reference)
#include <cuda_runtime.h>
#include <cstdint>

// QuantizedEmbedding: out[token, :] = dequant(weight[indices[token], :], scales[indices[token], :])
// R3: LDG gather + register dequant + smem staging + TMA bulk stores (cp.async.bulk),
// 4-deep output double buffering, 8 tokens per CTA (contiguous 128KB output per CTA).

static constexpr int PACKED    = 2048;    // packed int32 per row
static constexpr int NGROUPS   = 128;
static constexpr int DIM       = 4096;
static constexpr int THREADS   = 128;     // thread t owns group t (16 packed -> 32 floats)
static constexpr int TOK       = 8;       // tokens per CTA
static constexpr int NBUF      = 4;       // smem output buffers in flight
static constexpr int OUT_BYTES = DIM * 4; // 16384 per token
static constexpr int BUF_F4    = DIM / 4; // 1024 float4 per buffer
static constexpr int SMEM_BYTES = NBUF * OUT_BYTES;  // 64KB dynamic

__device__ __forceinline__ uint32_t smem_u32(const void* p) {
    return (uint32_t)__cvta_generic_to_shared(p);
}

__global__ void __launch_bounds__(THREADS)
qemb_kernel(const int* __restrict__ indices,
            const int* __restrict__ weight,
            const float* __restrict__ scales,
            float* __restrict__ out,
            int n_tokens)
{
    extern __shared__ float4 buf[];   // [NBUF][BUF_F4]
    int t = threadIdx.x;
    long base = (long)blockIdx.x * TOK;

    for (int i = 0; i < TOK; i++) {
        long tok = base + i;
        if (tok >= n_tokens) break;   // uniform across CTA

        int idx = __ldg(indices + tok);

        // thread t: packed [t*16, t*16+16) == exactly group t -> one scale
        const int4* wrow = reinterpret_cast<const int4*>(weight + (long)idx * PACKED) + t * 4;
        int4 w0 = __ldg(wrow + 0);
        int4 w1 = __ldg(wrow + 1);
        int4 w2 = __ldg(wrow + 2);
        int4 w3 = __ldg(wrow + 3);
        float s = __ldg(scales + (long)idx * NGROUPS + t);

        int w[16] = { w0.x, w0.y, w0.z, w0.w,
                      w1.x, w1.y, w1.z, w1.w,
                      w2.x, w2.y, w2.z, w2.w,
                      w3.x, w3.y, w3.z, w3.w };
        float4 o[8];
        #pragma unroll
        for (int j = 0; j < 8; j++) {
            int a = w[2 * j], b = w[2 * j + 1];
            o[j].x = (float)(a / 16 - 8) * s;      // trunc-toward-zero high nibble
            o[j].y = (float)((a & 15) - 8) * s;    // nonneg mod 16 low nibble
            o[j].z = (float)(b / 16 - 8) * s;
            o[j].w = (float)((b & 15) - 8) * s;
        }

        // stage into smem (xor-staggered order -> 4-phase floor, no extra conflicts)
        float4* bslot = buf + (size_t)(i & (NBUF - 1)) * BUF_F4 + t * 8;
        #pragma unroll
        for (int j = 0; j < 8; j++) {
            int jj = (j + t) & 7;
            bslot[jj] = o[jj];
        }
        __syncthreads();

        if (t == 0) {
            asm volatile("fence.proxy.async.shared::cta;" ::: "memory");
            uint32_t saddr = smem_u32(buf + (size_t)(i & (NBUF - 1)) * BUF_F4);
            void* g = (void*)(out + tok * DIM);
            int nbytes = OUT_BYTES;
            asm volatile("cp.async.bulk.global.shared::cta.bulk_group [%0], [%1], %2;"
                         :: "l"(g), "r"(saddr), "r"(nbytes) : "memory");
            asm volatile("cp.async.bulk.commit_group;" ::: "memory");
            // keep <= NBUF-1 groups pending so next iteration's buffer is free
            asm volatile("cp.async.bulk.wait_group %0;" :: "n"(NBUF - 1) : "memory");
        }
        __syncthreads();
    }

    // drain all pending bulk stores before kernel exit
    if (t == 0)
        asm volatile("cp.async.bulk.wait_group 0;" ::: "memory");
}

extern "C" void kernel_launch(void* const* d_in, const int* in_sizes, int n_in,
                              void* d_out, int out_size)
{
    const int*   indices = (const int*)d_in[0];
    const int*   weight  = (const int*)d_in[1];
    const float* scales  = (const float*)d_in[2];
    float*       out     = (float*)d_out;

    int n_tokens = in_sizes[0];  // 4*4096 = 16384

    cudaFuncSetAttribute(qemb_kernel,
                         cudaFuncAttributeMaxDynamicSharedMemorySize, SMEM_BYTES);

    int grid = (n_tokens + TOK - 1) / TOK;  // 2048
    qemb_kernel<<<grid, THREADS, SMEM_BYTES>>>(indices, weight, scales, out, n_tokens);
}

// round 4
// speedup vs baseline: 1.5443x; 1.5443x over previous
#include <cuda_runtime.h>
#include <cstdint>

// QuantizedEmbedding R4: R1's gather/dequant layout (256 thr, 2xLDG.128/thread)
// + TMA bulk stores from 2x16KB smem buffers (32KB total -> 7 CTAs/SM),
// 4 tokens per CTA, pipelined so buffer-wait overlaps LDG latency.

static constexpr int PACKED    = 2048;    // packed int32 per row
static constexpr int NGROUPS   = 128;
static constexpr int DIM       = 4096;
static constexpr int THREADS   = 256;     // thread t: packed [t*8, t*8+8) -> group t>>1
static constexpr int TOKS      = 4;       // tokens per CTA
static constexpr int NBUF      = 2;
static constexpr int OUT_BYTES = DIM * 4;            // 16384 B per token
static constexpr int BUF_F4    = DIM / 4;            // 1024 float4
static constexpr int SMEM_BYTES = NBUF * OUT_BYTES;  // 32KB

__device__ __forceinline__ void unpack2(int w, float s, float& e, float& o) {
    e = (float)(w / 16 - 8) * s;       // trunc-toward-zero high nibble
    o = (float)((w & 15) - 8) * s;     // nonneg mod-16 low nibble
}

__global__ void __launch_bounds__(THREADS)
qemb_kernel(const int* __restrict__ indices,
            const int* __restrict__ weight,
            const float* __restrict__ scales,
            float* __restrict__ out,
            int n_tokens)
{
    extern __shared__ float4 buf[];   // [NBUF][BUF_F4]
    int t = threadIdx.x;
    long base = (long)blockIdx.x * TOKS;
    int ntok = n_tokens - (int)base;
    if (ntok > TOKS) ntok = TOKS;

    for (int i = 0; i < ntok; i++) {
        long tok = base + i;
        int idx = __ldg(indices + tok);

        // issue all loads first; their latency overlaps the buffer-wait below
        const int4* wrow = reinterpret_cast<const int4*>(weight + (long)idx * PACKED) + t * 2;
        int4 w0 = __ldg(wrow);
        int4 w1 = __ldg(wrow + 1);
        float s = __ldg(scales + (long)idx * NGROUPS + (t >> 1));

        float4 o0, o1, o2, o3;
        unpack2(w0.x, s, o0.x, o0.y);
        unpack2(w0.y, s, o0.z, o0.w);
        unpack2(w0.z, s, o1.x, o1.y);
        unpack2(w0.w, s, o1.z, o1.w);
        unpack2(w1.x, s, o2.x, o2.y);
        unpack2(w1.y, s, o2.z, o2.w);
        unpack2(w1.z, s, o3.x, o3.y);
        unpack2(w1.w, s, o3.z, o3.w);

        // make sure this buffer's previous bulk store has been consumed
        if (i >= NBUF && t == 0)
            asm volatile("cp.async.bulk.wait_group %0;" :: "n"(NBUF - 1) : "memory");
        __syncthreads();

        float4* b = buf + (size_t)(i & (NBUF - 1)) * BUF_F4 + t * 4;
        b[0] = o0; b[1] = o1; b[2] = o2; b[3] = o3;
        __syncthreads();

        if (t == 0) {
            asm volatile("fence.proxy.async.shared::cta;" ::: "memory");
            uint32_t saddr = (uint32_t)__cvta_generic_to_shared(
                buf + (size_t)(i & (NBUF - 1)) * BUF_F4);
            void* g = (void*)(out + tok * DIM);
            asm volatile("cp.async.bulk.global.shared::cta.bulk_group [%0], [%1], %2;"
                         :: "l"(g), "r"(saddr), "n"(OUT_BYTES) : "memory");
            asm volatile("cp.async.bulk.commit_group;" ::: "memory");
        }
    }

    // drain pending bulk stores before exit
    if (t == 0)
        asm volatile("cp.async.bulk.wait_group 0;" ::: "memory");
}

extern "C" void kernel_launch(void* const* d_in, const int* in_sizes, int n_in,
                              void* d_out, int out_size)
{
    const int*   indices = (const int*)d_in[0];
    const int*   weight  = (const int*)d_in[1];
    const float* scales  = (const float*)d_in[2];
    float*       out     = (float*)d_out;

    int n_tokens = in_sizes[0];  // 16384

    cudaFuncSetAttribute(qemb_kernel,
                         cudaFuncAttributeMaxDynamicSharedMemorySize, SMEM_BYTES);

    int grid = (n_tokens + TOKS - 1) / TOKS;  // 4096
    qemb_kernel<<<grid, THREADS, SMEM_BYTES>>>(indices, weight, scales, out, n_tokens);
}

// round 5
// speedup vs baseline: 1.5817x; 1.0242x over previous
#include <cuda_runtime.h>
#include <cstdint>

// QuantizedEmbedding R5: warp-autonomous pipeline.
// Each of 8 warps owns a 2KB slice of each token's output row, double-buffers
// its own 2x2KB smem region, and issues its own cp.async.bulk store.
// No __syncthreads anywhere; next token's gather is prefetched before dequant.

static constexpr int PACKED   = 2048;    // packed int32 per row
static constexpr int NGROUPS  = 128;
static constexpr int DIM      = 4096;
static constexpr int THREADS  = 256;     // thread t: packed [t*8, t*8+8) -> group t>>1
static constexpr int TOKS     = 4;       // tokens per CTA
static constexpr int WARPS    = THREADS / 32;
static constexpr int SLICE_F  = DIM / WARPS;          // 512 floats = 2KB per warp slice
static constexpr int SLICE_B  = SLICE_F * 4;          // 2048 bytes
static constexpr int SMEM_BYTES = WARPS * 2 * SLICE_B; // 32KB

__device__ __forceinline__ void unpack2(int w, float s, float& e, float& o) {
    e = (float)(w / 16 - 8) * s;       // trunc-toward-zero high nibble
    o = (float)((w & 15) - 8) * s;     // nonneg mod-16 low nibble
}

__device__ __forceinline__ void dequant8(int4 w0, int4 w1, float s,
                                         float4& o0, float4& o1, float4& o2, float4& o3) {
    unpack2(w0.x, s, o0.x, o0.y);
    unpack2(w0.y, s, o0.z, o0.w);
    unpack2(w0.z, s, o1.x, o1.y);
    unpack2(w0.w, s, o1.z, o1.w);
    unpack2(w1.x, s, o2.x, o2.y);
    unpack2(w1.y, s, o2.z, o2.w);
    unpack2(w1.z, s, o3.x, o3.y);
    unpack2(w1.w, s, o3.z, o3.w);
}

__global__ void __launch_bounds__(THREADS)
qemb_kernel(const int* __restrict__ indices,
            const int* __restrict__ weight,
            const float* __restrict__ scales,
            float* __restrict__ out,
            int n_tokens)
{
    extern __shared__ float4 buf[];   // [WARPS][2][SLICE_F/4]
    int t    = threadIdx.x;
    int warp = t >> 5;
    int lane = t & 31;
    long base = (long)blockIdx.x * TOKS;
    int ntok = n_tokens - (int)base;
    if (ntok > TOKS) ntok = TOKS;
    if (ntok <= 0) return;

    // this warp's two smem buffers
    float4* wbuf = buf + (size_t)warp * 2 * (SLICE_F / 4);

    // prefetch token 0
    int idx = __ldg(indices + base);
    const int4* wrow = reinterpret_cast<const int4*>(weight + (long)idx * PACKED) + t * 2;
    int4 w0 = __ldg(wrow);
    int4 w1 = __ldg(wrow + 1);
    float s = __ldg(scales + (long)idx * NGROUPS + (t >> 1));

    for (int i = 0; i < ntok; i++) {
        // prefetch token i+1 while token i's data is consumed
        int4 n0, n1; float ns;
        if (i + 1 < ntok) {
            int idx2 = __ldg(indices + base + i + 1);
            const int4* wrow2 = reinterpret_cast<const int4*>(weight + (long)idx2 * PACKED) + t * 2;
            n0 = __ldg(wrow2);
            n1 = __ldg(wrow2 + 1);
            ns = __ldg(scales + (long)idx2 * NGROUPS + (t >> 1));
        }

        float4 o0, o1, o2, o3;
        dequant8(w0, w1, s, o0, o1, o2, o3);

        // reuse guard: buffer (i&1) was consumed by this warp's bulk store from iter i-2
        if (i >= 2 && lane == 0)
            asm volatile("cp.async.bulk.wait_group %0;" :: "n"(1) : "memory");
        __syncwarp();

        // stage this warp's 2KB slice: lane stores 4 consecutive float4
        float4* b = wbuf + (size_t)(i & 1) * (SLICE_F / 4) + lane * 4;
        b[0] = o0; b[1] = o1; b[2] = o2; b[3] = o3;

        asm volatile("fence.proxy.async.shared::cta;" ::: "memory");
        __syncwarp();

        if (lane == 0) {
            uint32_t saddr = (uint32_t)__cvta_generic_to_shared(
                wbuf + (size_t)(i & 1) * (SLICE_F / 4));
            void* g = (void*)(out + (base + i) * DIM + warp * SLICE_F);
            asm volatile("cp.async.bulk.global.shared::cta.bulk_group [%0], [%1], %2;"
                         :: "l"(g), "r"(saddr), "n"(SLICE_B) : "memory");
            asm volatile("cp.async.bulk.commit_group;" ::: "memory");
        }

        w0 = n0; w1 = n1; s = ns;
    }

    // drain this warp's pending bulk stores before exit
    if (lane == 0)
        asm volatile("cp.async.bulk.wait_group 0;" ::: "memory");
}

extern "C" void kernel_launch(void* const* d_in, const int* in_sizes, int n_in,
                              void* d_out, int out_size)
{
    const int*   indices = (const int*)d_in[0];
    const int*   weight  = (const int*)d_in[1];
    const float* scales  = (const float*)d_in[2];
    float*       out     = (float*)d_out;

    int n_tokens = in_sizes[0];  // 16384

    cudaFuncSetAttribute(qemb_kernel,
                         cudaFuncAttributeMaxDynamicSharedMemorySize, SMEM_BYTES);

    int grid = (n_tokens + TOKS - 1) / TOKS;  // 4096
    qemb_kernel<<<grid, THREADS, SMEM_BYTES>>>(indices, weight, scales, out, n_tokens);
}